// round 16
// baseline (speedup 1.0000x reference)
#include <cuda_runtime.h>
#include <cstdint>

#define THRESH 0.1f
#define TPB 256
#define IPT 16
#define CHUNK (TPB * IPT)     // 4096
#define STPB 1024
#define MAX_SEG 256
#define MAX_BLOCKS 8192
#define SENT 0xffffffffu
#define PADF __uint_as_float(0xffffffffu)   // -NaN: fails >THRESH, max as uint

// Scratch (no allocations allowed)
__device__ int      g_rs[MAX_SEG + 1];
__device__ unsigned g_segmin[MAX_SEG];
__device__ int      g_reppos[MAX_SEG];
__device__ int      g_blkoff[MAX_BLOCKS];
__device__ int      g_bseg0[MAX_BLOCKS];
__device__ unsigned g_bmin[2][MAX_BLOCKS];
__device__ int      g_bam[2][MAX_BLOCKS];    // first index achieving part min (k_fix)
__device__ int      g_beq[2][MAX_BLOCKS];    // count == part min (k_fix)
__device__ int      g_bct[2][MAX_BLOCKS];    // count > THRESH
__device__ int      g_bctb[2][MAX_BLOCKS];   // keeps before part argmin (k_fix)
__device__ unsigned g_mask[MAX_BLOCKS * TPB];// per-thread 16-bit (s>THRESH) mask

__device__ __forceinline__ int find_seg(int nseg, int i) {
    int lo = 0, hi = nseg;
    while (hi - lo > 1) {
        int mid = (lo + hi) >> 1;
        if (i >= g_rs[mid]) lo = mid; else hi = mid;
    }
    return lo;
}

__global__ void k_cfg(const int* __restrict__ raw, int nrs) {
    int t = threadIdx.x;
    __shared__ int is64;
    if (t == 0)
        is64 = (nrs > 2 && raw[1] == 0 && raw[2] != 0) ? 1 : 0;
    __syncthreads();
    if (t < nrs && t <= MAX_SEG) g_rs[t] = is64 ? raw[2 * t] : raw[t];
    if (t < MAX_SEG) {
        g_segmin[t] = 0x7f800000u;
        g_reppos[t] = 0;
    }
}

// interleaved float4: elem e of slot j -> idx = base + 4*(j*TPB+t) + e
__device__ __forceinline__ void load_chunk(const float* __restrict__ sc,
                                           int base, int n, int t, float* v, bool full) {
    if (full) {
        const float4* p = reinterpret_cast<const float4*>(sc + base);
#pragma unroll
        for (int j = 0; j < 4; j++) {
            float4 f = p[j * TPB + t];
            v[4 * j + 0] = f.x; v[4 * j + 1] = f.y;
            v[4 * j + 2] = f.z; v[4 * j + 3] = f.w;
        }
    } else {
#pragma unroll
        for (int j = 0; j < 4; j++)
#pragma unroll
            for (int e = 0; e < 4; e++) {
                int idx = base + 4 * (j * TPB + t) + e;
                v[4 * j + e] = (idx < n) ? sc[idx] : PADF;
            }
    }
}

// Pass 1 (light): one full read -> threshold mask + per-part {min, count>T}.
__global__ void __launch_bounds__(TPB) k_pass1(const float* __restrict__ sc,
                                               int n, int nseg) {
    int b = blockIdx.x, base = b * CHUNK;
    if (base >= n) return;
    int t = threadIdx.x, lane = t & 31, w = t >> 5;
    int seg0 = find_seg(nseg, base);
    int b1 = g_rs[seg0 + 1];
    bool full = (base + CHUNK <= n);
    bool oneseg = (b1 >= base + CHUNK) || (b1 >= n);

    float v[IPT];
    load_chunk(sc, base, n, t, v, full);

    unsigned tmask = 0;
#pragma unroll
    for (int k = 0; k < IPT; k++)
        tmask |= ((unsigned)(v[k] > THRESH)) << k;
    g_mask[b * TPB + t] = tmask;

    __shared__ unsigned smn[2][TPB / 32];
    __shared__ int sct[2][TPB / 32];

    if (oneseg) {
        unsigned mn = SENT;
#pragma unroll
        for (int k = 0; k < IPT; k++) mn = min(mn, __float_as_uint(v[k]));
        mn = __reduce_min_sync(~0u, mn);
        int ct = __reduce_add_sync(~0u, __popc(tmask));
        if (lane == 0) { smn[0][w] = mn; sct[0][w] = ct; }
        __syncthreads();
        if (t == 0) {
            unsigned M = smn[0][0]; int C = sct[0][0];
#pragma unroll
            for (int i = 1; i < TPB / 32; i++) { M = min(M, smn[0][i]); C += sct[0][i]; }
            g_bmin[0][b] = M; g_bct[0][b] = C;
            g_bmin[1][b] = SENT; g_bct[1][b] = 0;
            g_beq[0][b] = 0; g_beq[1][b] = 0;
            g_bam[0][b] = 0x7fffffff; g_bam[1][b] = 0x7fffffff;
            g_bctb[0][b] = 0; g_bctb[1][b] = 0;
            g_bseg0[b] = seg0;
            atomicMin(&g_segmin[seg0], M);
        }
        return;
    }

    // boundary block (rare, always full since tail block is oneseg)
    unsigned mn0 = SENT, mn1 = SENT;
    int ct0 = 0, ct1 = 0;
#pragma unroll
    for (int j = 0; j < 4; j++)
#pragma unroll
        for (int e = 0; e < 4; e++) {
            int idx = base + 4 * (j * TPB + t) + e;
            float s = v[4 * j + e];
            unsigned bb = __float_as_uint(s);
            if (idx < b1) { mn0 = min(mn0, bb); ct0 += (int)(s > THRESH); }
            else          { mn1 = min(mn1, bb); ct1 += (int)(s > THRESH); }
        }
    mn0 = __reduce_min_sync(~0u, mn0); mn1 = __reduce_min_sync(~0u, mn1);
    ct0 = __reduce_add_sync(~0u, ct0); ct1 = __reduce_add_sync(~0u, ct1);
    if (lane == 0) { smn[0][w] = mn0; sct[0][w] = ct0; smn[1][w] = mn1; sct[1][w] = ct1; }
    __syncthreads();
    if (t == 0) {
#pragma unroll
        for (int p = 0; p < 2; p++) {
            unsigned M = smn[p][0]; int C = sct[p][0];
#pragma unroll
            for (int i = 1; i < TPB / 32; i++) { M = min(M, smn[p][i]); C += sct[p][i]; }
            g_bmin[p][b] = M; g_bct[p][b] = C;
            g_beq[p][b] = 0; g_bam[p][b] = 0x7fffffff; g_bctb[p][b] = 0;
            if (M != SENT && seg0 + p < nseg) atomicMin(&g_segmin[seg0 + p], M);
        }
        g_bseg0[b] = seg0;
    }
}

// k_fix: per segment, fill eq/am/ctb for the (few) blocks whose part-min == segmin.
__global__ void __launch_bounds__(TPB) k_fix(const float* __restrict__ sc,
                                             int n, int nseg) {
    int s = blockIdx.x;
    if (s >= nseg) return;
    int t = threadIdx.x, lane = t & 31, w = t >> 5;
    int segstart = g_rs[s], segend = min(g_rs[s + 1], n);
    if (segend <= segstart) return;
    unsigned sm = g_segmin[s];
    int bs = segstart / CHUNK, be = (segend - 1) / CHUNK;

    __shared__ int seqw[TPB / 32];
    __shared__ unsigned samw[TPB / 32];
    __shared__ int s_eq, s_am;

    for (int b = bs; b <= be; b++) {
#pragma unroll
        for (int p = 0; p < 2; p++) {
            if (g_bseg0[b] + p != s) continue;        // uniform per block
            if (g_bmin[p][b] != sm) continue;         // uniform
            int base = b * CHUNK;
            int plo = max(base, segstart);
            int phi = min(base + CHUNK, segend);
            int eq = 0; unsigned am = 0xffffffffu;
            for (int idx = plo + t; idx < phi; idx += TPB) {
                if (__float_as_uint(sc[idx]) == sm) { eq++; am = min(am, (unsigned)idx); }
            }
            eq = __reduce_add_sync(~0u, eq);
            am = __reduce_min_sync(~0u, am);
            if (lane == 0) { seqw[w] = eq; samw[w] = am; }
            __syncthreads();
            if (t == 0) {
                int E = 0; unsigned A = 0xffffffffu;
#pragma unroll
                for (int i = 0; i < TPB / 32; i++) { E += seqw[i]; A = min(A, samw[i]); }
                s_eq = E; s_am = (int)A;
            }
            __syncthreads();
            int A = s_am;
            int cb = 0;
            for (int idx = plo + t; idx < A; idx += TPB)
                cb += (int)(sc[idx] > THRESH);
            cb = __reduce_add_sync(~0u, cb);
            if (lane == 0) seqw[w] = cb;
            __syncthreads();
            if (t == 0) {
                int C = 0;
#pragma unroll
                for (int i = 0; i < TPB / 32; i++) C += seqw[i];
                g_beq[p][b] = s_eq; g_bam[p][b] = s_am; g_bctb[p][b] = C;
            }
            __syncthreads();
        }
    }
}

// Pass 2: metadata only. blkoff scan + newrs + reppos.
__global__ void __launch_bounds__(STPB) k_scan2(int nblocks, int nseg,
                                                float* __restrict__ out,
                                                int off_nr, int osz) {
    __shared__ int wsum[STPB / 32];
    __shared__ int s_carry;
    __shared__ int s_segcnt[MAX_SEG];
    __shared__ int s_argmin[MAX_SEG];
    int t = threadIdx.x, lane = t & 31, w = t >> 5;
    for (int s = t; s < MAX_SEG; s += STPB) { s_segcnt[s] = 0; s_argmin[s] = 0x7fffffff; }
    if (t == 0) s_carry = 0;
    __syncthreads();
    for (int start = 0; start < nblocks; start += STPB) {
        int i = start + t;
        int v = 0;
        if (i < nblocks) {
            int seg0 = g_bseg0[i];
            unsigned m0 = g_bmin[0][i], m1 = g_bmin[1][i];
            int k0 = g_bct[0][i], k1 = g_bct[1][i];
            if (m0 != SENT && m0 == g_segmin[seg0] && __uint_as_float(m0) <= THRESH)
                k0 += g_beq[0][i];
            if (seg0 + 1 < nseg && m1 != SENT && m1 == g_segmin[seg0 + 1] &&
                __uint_as_float(m1) <= THRESH)
                k1 += g_beq[1][i];
            v = k0 + k1;
            if (k0) atomicAdd(&s_segcnt[seg0], k0);
            if (k1 && seg0 + 1 < nseg) atomicAdd(&s_segcnt[seg0 + 1], k1);
            if (m0 != SENT && m0 == g_segmin[seg0])
                atomicMin(&s_argmin[seg0], g_bam[0][i]);
            if (seg0 + 1 < nseg && m1 != SENT && m1 == g_segmin[seg0 + 1])
                atomicMin(&s_argmin[seg0 + 1], g_bam[1][i]);
        }
        int x = v;
#pragma unroll
        for (int o = 1; o < 32; o <<= 1) {
            int y = __shfl_up_sync(~0u, x, o);
            if (lane >= o) x += y;
        }
        if (lane == 31) wsum[w] = x;
        __syncthreads();
        int wbase = 0, total = 0;
#pragma unroll
        for (int j = 0; j < STPB / 32; j++) {
            if (j < w) wbase += wsum[j];
            total += wsum[j];
        }
        int carry = s_carry;
        if (i < nblocks) g_blkoff[i] = carry + wbase + x - v;
        __syncthreads();
        if (t == 0) s_carry = carry + total;
        __syncthreads();
    }
    for (int i = t; i < nblocks; i += STPB) {
        int seg0 = g_bseg0[i];
        unsigned m0 = g_bmin[0][i], m1 = g_bmin[1][i];
        if (m0 != SENT && m0 == g_segmin[seg0] && g_bam[0][i] == s_argmin[seg0])
            g_reppos[seg0] = g_blkoff[i] + g_bctb[0][i];
        if (seg0 + 1 < nseg && m1 != SENT && m1 == g_segmin[seg0 + 1] &&
            g_bam[1][i] == s_argmin[seg0 + 1]) {
            int k0 = g_bct[0][i];
            if (m0 != SENT && m0 == g_segmin[seg0] && __uint_as_float(m0) <= THRESH)
                k0 += g_beq[0][i];
            g_reppos[seg0 + 1] = g_blkoff[i] + k0 + g_bctb[1][i];
        }
    }
    if (t == 0 && off_nr >= 0 && off_nr + nseg < osz) {
        int acc = 0;
        out[off_nr] = 0.0f;
        for (int s = 0; s < nseg; s++) { acc += s_segcnt[s]; out[off_nr + 1 + s] = (float)acc; }
    }
}

// coalesced smem->gmem copy, arbitrary 4B-aligned dst, vectorized with funnel.
// sbuf must have >= 8 floats of padding beyond len.
__device__ __forceinline__ void smem_to_gmem(const float* __restrict__ sbuf,
                                             float* __restrict__ gdst, int len, int t) {
    if (len <= 0) return;
    if (len < 16) {
        for (int i = t; i < len; i += TPB) gdst[i] = sbuf[i];
        return;
    }
    int r0 = (int)((4 - ((((unsigned long long)(gdst)) >> 2) & 3ull)) & 3ull);
    const float4* sb4 = reinterpret_cast<const float4*>(sbuf);
    if (r0 == 0) {
        int nq = len >> 2;
        float4* og = reinterpret_cast<float4*>(gdst);
        for (int q = t; q < nq; q += TPB) og[q] = sb4[q];
        for (int i = (nq << 2) + t; i < len; i += TPB) gdst[i] = sbuf[i];
    } else {
        if (t < r0) gdst[t] = sbuf[t];
        int nq = (len - r0) >> 2;
        for (int q = t; q < nq; q += TPB) {
            float4 a = sb4[q], c = sb4[q + 1];
            float4 o4;
            if (r0 == 1)      o4 = make_float4(a.y, a.z, a.w, c.x);
            else if (r0 == 2) o4 = make_float4(a.z, a.w, c.x, c.y);
            else              o4 = make_float4(a.w, c.x, c.y, c.z);
            *reinterpret_cast<float4*>(gdst + r0 + 4 * q) = o4;
        }
        for (int i = r0 + (nq << 2) + t; i < len; i += TPB) gdst[i] = sbuf[i];
    }
}

// Pass 3: mask-driven compaction + backgather; both outputs staged + vectorized.
__global__ void __launch_bounds__(TPB) k_write(const float* __restrict__ sc,
                                               int n, int nseg,
                                               float* __restrict__ out,
                                               int off_sel, int cap_sel,
                                               int off_bg, int osz) {
    __shared__ float s_sel[CHUNK + 8];
    __shared__ float s_bg[CHUNK + 8];
    __shared__ int s_wt[4][TPB / 32];
    __shared__ int s_off[32];
    __shared__ int s_tot;
    int b = blockIdx.x, base = b * CHUNK;
    if (base >= n) return;
    int t = threadIdx.x, lane = t & 31, w = t >> 5;
    int seg0 = g_bseg0[b];
    int b1 = g_rs[seg0 + 1];
    unsigned min0 = g_segmin[seg0];
    unsigned min1 = (seg0 + 1 < nseg) ? g_segmin[seg0 + 1] : SENT;
    int rep0 = g_reppos[seg0];
    int rep1 = (seg0 + 1 < nseg) ? g_reppos[seg0 + 1] : 0;
    bool full = (base + CHUNK <= n);
    bool oneseg = (b1 >= base + CHUNK) || (b1 >= n);

    unsigned tmask = g_mask[b * TPB + t];

    bool need0 = (g_bmin[0][b] == min0) && (__uint_as_float(min0) <= THRESH);
    bool need1 = (!oneseg) && (seg0 + 1 < nseg) &&
                 (g_bmin[1][b] == min1) && (__uint_as_float(min1) <= THRESH);
    if (need0 || need1) {
        float v[IPT];
        load_chunk(sc, base, n, t, v, full);
#pragma unroll
        for (int j = 0; j < 4; j++)
#pragma unroll
            for (int e = 0; e < 4; e++) {
                int idx = base + 4 * (j * TPB + t) + e;
                unsigned bits = __float_as_uint(v[4 * j + e]);
                bool p0 = oneseg || (idx < b1);
                bool hit = p0 ? (need0 && bits == min0) : (need1 && bits == min1);
                if (hit) tmask |= 1u << (4 * j + e);
            }
    }

    unsigned km[4];
    int pack = 0;
#pragma unroll
    for (int j = 0; j < 4; j++) {
        km[j] = (tmask >> (4 * j)) & 15u;
        pack += __popc(km[j]) << (8 * j);
    }

    int x = pack;
#pragma unroll
    for (int o = 1; o < 32; o <<= 1) {
        int y = __shfl_up_sync(~0u, x, o);
        if (lane >= o) x += y;
    }
    int excl = x - pack;
    if (lane == 31) {
#pragma unroll
        for (int j = 0; j < 4; j++) s_wt[j][w] = (x >> (8 * j)) & 255;
    }
    __syncthreads();
    if (t < 32) {
        int val = s_wt[t >> 3][t & 7];    // order (j, w): l = j*8 + w
        int xx = val;
#pragma unroll
        for (int o = 1; o < 32; o <<= 1) {
            int y = __shfl_up_sync(~0u, xx, o);
            if ((t & 31) >= o) xx += y;
        }
        s_off[t] = xx - val;
        if (t == 31) s_tot = xx;
    }
    __syncthreads();

    int blkoff = g_blkoff[b];
#pragma unroll
    for (int j = 0; j < 4; j++) {
        int lpos0 = s_off[j * 8 + w] + ((excl >> (8 * j)) & 255);
        float bgv[4];
#pragma unroll
        for (int e = 0; e < 4; e++) {
            int idx = base + 4 * (j * TPB + t) + e;
            bool keep = (km[j] >> e) & 1u;
            int inner = __popc(km[j] & ((1u << e) - 1u));
            int lp = lpos0 + inner;
            if (keep) s_sel[lp] = (float)idx;
            int rep = (oneseg || idx < b1) ? rep0 : rep1;
            bgv[e] = (float)(keep ? (blkoff + lp) : rep);
        }
        float4* sb = reinterpret_cast<float4*>(s_bg);
        sb[j * TPB + t] = make_float4(bgv[0], bgv[1], bgv[2], bgv[3]);
    }
    __syncthreads();

    if (off_sel >= 0) {
        int len = min(s_tot, cap_sel - blkoff);
        smem_to_gmem(s_sel, out + off_sel + blkoff, len, t);
    }
    if (off_bg >= 0) {
        if (full) {
            smem_to_gmem(s_bg, out + off_bg + base, CHUNK, t);
        } else {
            int lim = n - base;
            int gbase = off_bg + base;
            for (int i = t; i < lim; i += TPB) {
                int o2 = gbase + i;
                if (o2 < osz) out[o2] = s_bg[i];
            }
        }
    }
}

extern "C" void kernel_launch(void* const* d_in, const int* in_sizes, int n_in,
                              void* d_out, int out_size) {
    int i_sc = 0;
    for (int i = 1; i < n_in; i++) if (in_sizes[i] > in_sizes[i_sc]) i_sc = i;
    int i_rs = (i_sc == 0 && n_in > 1) ? 1 : 0;
    for (int i = 0; i < n_in; i++)
        if (i != i_sc && in_sizes[i] >= 2 && in_sizes[i] <= MAX_SEG + 1) { i_rs = i; break; }

    const float* sc    = (const float*)d_in[i_sc];
    const int*   rsraw = (const int*)d_in[i_rs];
    int n    = in_sizes[i_sc];
    int nseg = in_sizes[i_rs] - 1;
    if (nseg > MAX_SEG) nseg = MAX_SEG;
    if (nseg < 1) nseg = 1;
    int nblocks = (n + CHUNK - 1) / CHUNK;
    if (nblocks > MAX_BLOCKS) nblocks = MAX_BLOCKS;
    float* out = (float*)d_out;

    int off_sel = -1, cap_sel = 0, off_nr = -1, off_bg = -1;
    if (out_size >= n + nseg + 1) {            // [sel | newrs | backgather]
        cap_sel = out_size - n - (nseg + 1);
        off_sel = 0; off_nr = cap_sel; off_bg = cap_sel + nseg + 1;
    } else if (out_size == nseg + 1) {
        off_nr = 0;
    } else if (out_size == n) {
        off_bg = 0;
    } else {
        off_sel = 0; cap_sel = out_size;
    }

    k_cfg<<<1, 256>>>(rsraw, nseg + 1);
    k_pass1<<<nblocks, TPB>>>(sc, n, nseg);
    k_fix<<<nseg, TPB>>>(sc, n, nseg);
    k_scan2<<<1, STPB>>>(nblocks, nseg, out, off_nr, out_size);
    k_write<<<nblocks, TPB>>>(sc, n, nseg, out, off_sel, cap_sel, off_bg, out_size);
}

// round 17
// speedup vs baseline: 1.3218x; 1.3218x over previous
#include <cuda_runtime.h>
#include <cstdint>

#define THRESH 0.1f
#define TPB 256
#define IPT 16
#define CHUNK (TPB * IPT)     // 4096
#define STPB 1024
#define MAX_SEG 256
#define MAX_BLOCKS 8192
#define MAX_TRIPS (MAX_BLOCKS / STPB)
#define SENT 0xffffffffu
#define PADF __uint_as_float(0xffffffffu)   // -NaN: fails >THRESH, max as uint

// Scratch (no allocations allowed)
__device__ int      g_rs[MAX_SEG + 1];
__device__ unsigned g_segmin[MAX_SEG];
__device__ int      g_reppos[MAX_SEG];
__device__ int      g_repblk[MAX_SEG];   // argmin block per segment (-1 = none)
__device__ int      g_repp[MAX_SEG];     // part (0/1) of argmin within that block
__device__ int      g_repctb[MAX_SEG];   // keeps before argmin within that part
__device__ int      g_blkoff[MAX_BLOCKS];
__device__ int      g_bseg0[MAX_BLOCKS];
__device__ unsigned g_bmin[2][MAX_BLOCKS];
__device__ int      g_bcnt[MAX_BLOCKS];  // adjusted total keep count per block
__device__ int      g_bk0[MAX_BLOCKS];   // adjusted part0 keep count per block
__device__ unsigned g_mask[MAX_BLOCKS * TPB];

__device__ __forceinline__ int find_seg(int nseg, int i) {
    int lo = 0, hi = nseg;
    while (hi - lo > 1) {
        int mid = (lo + hi) >> 1;
        if (i >= g_rs[mid]) lo = mid; else hi = mid;
    }
    return lo;
}

__global__ void k_cfg(const int* __restrict__ raw, int nrs) {
    int t = threadIdx.x;
    __shared__ int is64;
    if (t == 0)
        is64 = (nrs > 2 && raw[1] == 0 && raw[2] != 0) ? 1 : 0;
    __syncthreads();
    if (t < nrs && t <= MAX_SEG) g_rs[t] = is64 ? raw[2 * t] : raw[t];
    if (t < MAX_SEG) {
        g_segmin[t] = 0x7f800000u;
        g_reppos[t] = 0;
        g_repblk[t] = -1;
    }
}

// interleaved float4: elem e of slot j -> idx = base + 4*(j*TPB+t) + e
__device__ __forceinline__ void load_chunk(const float* __restrict__ sc,
                                           int base, int n, int t, float* v, bool full) {
    if (full) {
        const float4* p = reinterpret_cast<const float4*>(sc + base);
#pragma unroll
        for (int j = 0; j < 4; j++) {
            float4 f = p[j * TPB + t];
            v[4 * j + 0] = f.x; v[4 * j + 1] = f.y;
            v[4 * j + 2] = f.z; v[4 * j + 3] = f.w;
        }
    } else {
#pragma unroll
        for (int j = 0; j < 4; j++)
#pragma unroll
            for (int e = 0; e < 4; e++) {
                int idx = base + 4 * (j * TPB + t) + e;
                v[4 * j + e] = (idx < n) ? sc[idx] : PADF;
            }
    }
}

// Pass 1: one full read -> mask + per-part min + block counts.
__global__ void __launch_bounds__(TPB) k_pass1(const float* __restrict__ sc,
                                               int n, int nseg) {
    int b = blockIdx.x, base = b * CHUNK;
    if (base >= n) return;
    int t = threadIdx.x, lane = t & 31, w = t >> 5;
    int seg0 = find_seg(nseg, base);
    int b1 = g_rs[seg0 + 1];
    bool full = (base + CHUNK <= n);
    bool oneseg = (b1 >= base + CHUNK) || (b1 >= n);

    float v[IPT];
    load_chunk(sc, base, n, t, v, full);

    unsigned tmask = 0;
#pragma unroll
    for (int k = 0; k < IPT; k++)
        tmask |= ((unsigned)(v[k] > THRESH)) << k;
    g_mask[b * TPB + t] = tmask;

    __shared__ unsigned smn[2][TPB / 32];
    __shared__ int sct[2][TPB / 32];

    if (oneseg) {
        unsigned mn = SENT;
#pragma unroll
        for (int k = 0; k < IPT; k++) mn = min(mn, __float_as_uint(v[k]));
        mn = __reduce_min_sync(~0u, mn);
        int ct = __reduce_add_sync(~0u, __popc(tmask));
        if (lane == 0) { smn[0][w] = mn; sct[0][w] = ct; }
        __syncthreads();
        if (t == 0) {
            unsigned M = smn[0][0]; int C = sct[0][0];
#pragma unroll
            for (int i = 1; i < TPB / 32; i++) { M = min(M, smn[0][i]); C += sct[0][i]; }
            g_bmin[0][b] = M; g_bmin[1][b] = SENT;
            g_bcnt[b] = C; g_bk0[b] = C;
            g_bseg0[b] = seg0;
            atomicMin(&g_segmin[seg0], M);
        }
        return;
    }

    // boundary block (rare)
    unsigned mn0 = SENT, mn1 = SENT;
    int ct0 = 0, ct1 = 0;
#pragma unroll
    for (int j = 0; j < 4; j++)
#pragma unroll
        for (int e = 0; e < 4; e++) {
            int idx = base + 4 * (j * TPB + t) + e;
            float s = v[4 * j + e];
            unsigned bb = __float_as_uint(s);
            if (idx < b1) { mn0 = min(mn0, bb); ct0 += (int)(s > THRESH); }
            else          { mn1 = min(mn1, bb); ct1 += (int)(s > THRESH); }
        }
    mn0 = __reduce_min_sync(~0u, mn0); mn1 = __reduce_min_sync(~0u, mn1);
    ct0 = __reduce_add_sync(~0u, ct0); ct1 = __reduce_add_sync(~0u, ct1);
    if (lane == 0) { smn[0][w] = mn0; sct[0][w] = ct0; smn[1][w] = mn1; sct[1][w] = ct1; }
    __syncthreads();
    if (t == 0) {
        unsigned M0 = smn[0][0], M1 = smn[1][0];
        int C0 = sct[0][0], C1 = sct[1][0];
#pragma unroll
        for (int i = 1; i < TPB / 32; i++) {
            M0 = min(M0, smn[0][i]); C0 += sct[0][i];
            M1 = min(M1, smn[1][i]); C1 += sct[1][i];
        }
        g_bmin[0][b] = M0; g_bmin[1][b] = M1;
        g_bcnt[b] = C0 + C1; g_bk0[b] = C0;
        g_bseg0[b] = seg0;
        if (M0 != SENT) atomicMin(&g_segmin[seg0], M0);
        if (M1 != SENT && seg0 + 1 < nseg) atomicMin(&g_segmin[seg0 + 1], M1);
    }
}

// k_fix: per segment (parallel over its blocks): fold ties into counts; record argmin.
__global__ void __launch_bounds__(TPB) k_fix(const float* __restrict__ sc,
                                             int n, int nseg) {
    int s = blockIdx.x;
    if (s >= nseg) return;
    int t = threadIdx.x;
    int segstart = g_rs[s], segend = min(g_rs[s + 1], n);
    if (segend <= segstart) return;
    unsigned sm = g_segmin[s];
    int bs = segstart / CHUNK, be = (segend - 1) / CHUNK;
    bool adj = (__uint_as_float(sm) <= THRESH);

    __shared__ int s_match[128];
    __shared__ int s_nm, s_am, s_red;

    if (t == 0) { s_nm = 0; s_am = 0x7fffffff; }
    __syncthreads();
    // parallel matching-block search
    for (int b = bs + t; b <= be; b += TPB) {
        int p = (g_bseg0[b] == s) ? 0 : 1;
        if (g_bmin[p][b] == sm) {
            int slot = atomicAdd(&s_nm, 1);
            if (slot < 128) s_match[slot] = (b << 1) | p;
        }
    }
    __syncthreads();
    int nm = min(s_nm, 128);

    // per matched block: eq count + local argmin
    for (int i = 0; i < nm; i++) {
        int bp = s_match[i], b = bp >> 1, p = bp & 1;
        int base = b * CHUNK;
        int plo = max(base, segstart);
        int phi = min(base + CHUNK, segend);
        int eq = 0; unsigned am = 0xffffffffu;
        for (int idx = plo + t; idx < phi; idx += TPB) {
            if (__float_as_uint(sc[idx]) == sm) { eq++; am = min(am, (unsigned)idx); }
        }
        eq = __reduce_add_sync(~0u, eq);
        am = __reduce_min_sync(~0u, am);
        if ((t & 31) == 0) {
            if (eq && adj) {
                atomicAdd(&g_bcnt[b], eq);
                if (p == 0) atomicAdd(&g_bk0[b], eq);
            }
            if (am != 0xffffffffu) atomicMin(&s_am, (int)am);
        }
    }
    __syncthreads();
    int am = s_am;
    if (am == 0x7fffffff) return;   // should not happen
    int ab = am / CHUNK;
    int ap = (g_bseg0[ab] == s) ? 0 : 1;
    int plo = max(ab * CHUNK, segstart);
    if (t == 0) s_red = 0;
    __syncthreads();
    int cb = 0;
    for (int idx = plo + t; idx < am; idx += TPB)
        cb += (int)(sc[idx] > THRESH);
    cb = __reduce_add_sync(~0u, cb);
    if ((t & 31) == 0 && cb) atomicAdd(&s_red, cb);
    __syncthreads();
    if (t == 0) {
        g_repblk[s] = ab; g_repp[s] = ap; g_repctb[s] = s_red;
    }
}

// Pass 2: single-block scan of g_bcnt (values preloaded) + newrs + reppos.
__global__ void __launch_bounds__(STPB) k_scan2(int nblocks, int nseg,
                                                float* __restrict__ out,
                                                int off_nr, int osz, int n) {
    __shared__ int wsum[STPB / 32];
    __shared__ int s_tot;
    int t = threadIdx.x, lane = t & 31, w = t >> 5;
    int trips = (nblocks + STPB - 1) / STPB;

    int v[MAX_TRIPS];
#pragma unroll
    for (int r = 0; r < MAX_TRIPS; r++) {
        int i = r * STPB + t;
        v[r] = (i < nblocks) ? g_bcnt[i] : 0;      // all loads issued upfront
    }

    int carry = 0;
    for (int r = 0; r < trips; r++) {
        int x = v[r];
#pragma unroll
        for (int o = 1; o < 32; o <<= 1) {
            int y = __shfl_up_sync(~0u, x, o);
            if (lane >= o) x += y;
        }
        if (lane == 31) wsum[w] = x;
        __syncthreads();
        if (t < 32) {
            int val = wsum[t];
            int xx = val;
#pragma unroll
            for (int o = 1; o < 32; o <<= 1) {
                int y = __shfl_up_sync(~0u, xx, o);
                if (t >= o) xx += y;
            }
            wsum[t] = xx - val;                    // exclusive warp base
            if (t == 31) s_tot = xx;
        }
        __syncthreads();
        int i = r * STPB + t;
        if (i < nblocks) g_blkoff[i] = carry + wsum[w] + x - v[r];
        carry += s_tot;
        __syncthreads();
    }

    // newrs: cumulative keep-prefix at each segment end (from blkoff + part0 count)
    if (off_nr >= 0 && off_nr + nseg < osz) {
        if (t == 0) out[off_nr] = 0.0f;
        for (int s = t; s < nseg; s += STPB) {
            int e = g_rs[s + 1]; if (e > n) e = n;
            int prefix = 0;
            if (e > 0) {
                int b = (e - 1) / CHUNK;
                prefix = g_blkoff[b] + g_bk0[b];
            }
            out[off_nr + 1 + s] = (float)prefix;
        }
    }
    // reppos
    for (int s = t; s < nseg; s += STPB) {
        int ab = g_repblk[s];
        if (ab < 0) { g_reppos[s] = 0; continue; }
        int rp = g_blkoff[ab] + g_repctb[s];
        if (g_repp[s]) rp += g_bk0[ab];
        g_reppos[s] = rp;
    }
}

// coalesced smem->gmem copy, arbitrary 4B-aligned dst, vectorized with funnel.
__device__ __forceinline__ void smem_to_gmem(const float* __restrict__ sbuf,
                                             float* __restrict__ gdst, int len, int t) {
    if (len <= 0) return;
    if (len < 16) {
        for (int i = t; i < len; i += TPB) gdst[i] = sbuf[i];
        return;
    }
    int r0 = (int)((4 - ((((unsigned long long)(gdst)) >> 2) & 3ull)) & 3ull);
    const float4* sb4 = reinterpret_cast<const float4*>(sbuf);
    if (r0 == 0) {
        int nq = len >> 2;
        float4* og = reinterpret_cast<float4*>(gdst);
        for (int q = t; q < nq; q += TPB) og[q] = sb4[q];
        for (int i = (nq << 2) + t; i < len; i += TPB) gdst[i] = sbuf[i];
    } else {
        if (t < r0) gdst[t] = sbuf[t];
        int nq = (len - r0) >> 2;
        for (int q = t; q < nq; q += TPB) {
            float4 a = sb4[q], c = sb4[q + 1];
            float4 o4;
            if (r0 == 1)      o4 = make_float4(a.y, a.z, a.w, c.x);
            else if (r0 == 2) o4 = make_float4(a.z, a.w, c.x, c.y);
            else              o4 = make_float4(a.w, c.x, c.y, c.z);
            *reinterpret_cast<float4*>(gdst + r0 + 4 * q) = o4;
        }
        for (int i = r0 + (nq << 2) + t; i < len; i += TPB) gdst[i] = sbuf[i];
    }
}

// Pass 3: mask-driven compaction + backgather; both outputs staged + vectorized.
__global__ void __launch_bounds__(TPB) k_write(const float* __restrict__ sc,
                                               int n, int nseg,
                                               float* __restrict__ out,
                                               int off_sel, int cap_sel,
                                               int off_bg, int osz) {
    __shared__ float s_sel[CHUNK + 8];
    __shared__ float s_bg[CHUNK + 8];
    __shared__ int s_wt[4][TPB / 32];
    __shared__ int s_off[32];
    __shared__ int s_tot;
    int b = blockIdx.x, base = b * CHUNK;
    if (base >= n) return;
    int t = threadIdx.x, lane = t & 31, w = t >> 5;
    int seg0 = g_bseg0[b];
    int b1 = g_rs[seg0 + 1];
    unsigned min0 = g_segmin[seg0];
    unsigned min1 = (seg0 + 1 < nseg) ? g_segmin[seg0 + 1] : SENT;
    int rep0 = g_reppos[seg0];
    int rep1 = (seg0 + 1 < nseg) ? g_reppos[seg0 + 1] : 0;
    bool full = (base + CHUNK <= n);
    bool oneseg = (b1 >= base + CHUNK) || (b1 >= n);

    unsigned tmask = g_mask[b * TPB + t];

    bool need0 = (g_bmin[0][b] == min0) && (__uint_as_float(min0) <= THRESH);
    bool need1 = (!oneseg) && (seg0 + 1 < nseg) &&
                 (g_bmin[1][b] == min1) && (__uint_as_float(min1) <= THRESH);
    if (need0 || need1) {
        float v[IPT];
        load_chunk(sc, base, n, t, v, full);
#pragma unroll
        for (int j = 0; j < 4; j++)
#pragma unroll
            for (int e = 0; e < 4; e++) {
                int idx = base + 4 * (j * TPB + t) + e;
                unsigned bits = __float_as_uint(v[4 * j + e]);
                bool p0 = oneseg || (idx < b1);
                bool hit = p0 ? (need0 && bits == min0) : (need1 && bits == min1);
                if (hit) tmask |= 1u << (4 * j + e);
            }
    }

    unsigned km[4];
    int pack = 0;
#pragma unroll
    for (int j = 0; j < 4; j++) {
        km[j] = (tmask >> (4 * j)) & 15u;
        pack += __popc(km[j]) << (8 * j);
    }

    int x = pack;
#pragma unroll
    for (int o = 1; o < 32; o <<= 1) {
        int y = __shfl_up_sync(~0u, x, o);
        if (lane >= o) x += y;
    }
    int excl = x - pack;
    if (lane == 31) {
#pragma unroll
        for (int j = 0; j < 4; j++) s_wt[j][w] = (x >> (8 * j)) & 255;
    }
    __syncthreads();
    if (t < 32) {
        int val = s_wt[t >> 3][t & 7];    // order (j, w): l = j*8 + w
        int xx = val;
#pragma unroll
        for (int o = 1; o < 32; o <<= 1) {
            int y = __shfl_up_sync(~0u, xx, o);
            if ((t & 31) >= o) xx += y;
        }
        s_off[t] = xx - val;
        if (t == 31) s_tot = xx;
    }
    __syncthreads();

    int blkoff = g_blkoff[b];
#pragma unroll
    for (int j = 0; j < 4; j++) {
        int lpos0 = s_off[j * 8 + w] + ((excl >> (8 * j)) & 255);
        float bgv[4];
#pragma unroll
        for (int e = 0; e < 4; e++) {
            int idx = base + 4 * (j * TPB + t) + e;
            bool keep = (km[j] >> e) & 1u;
            int inner = __popc(km[j] & ((1u << e) - 1u));
            int lp = lpos0 + inner;
            if (keep) s_sel[lp] = (float)idx;
            int rep = (oneseg || idx < b1) ? rep0 : rep1;
            bgv[e] = (float)(keep ? (blkoff + lp) : rep);
        }
        float4* sb = reinterpret_cast<float4*>(s_bg);
        sb[j * TPB + t] = make_float4(bgv[0], bgv[1], bgv[2], bgv[3]);
    }
    __syncthreads();

    if (off_sel >= 0) {
        int len = min(s_tot, cap_sel - blkoff);
        smem_to_gmem(s_sel, out + off_sel + blkoff, len, t);
    }
    if (off_bg >= 0) {
        if (full) {
            smem_to_gmem(s_bg, out + off_bg + base, CHUNK, t);
        } else {
            int lim = n - base;
            int gbase = off_bg + base;
            for (int i = t; i < lim; i += TPB) {
                int o2 = gbase + i;
                if (o2 < osz) out[o2] = s_bg[i];
            }
        }
    }
}

extern "C" void kernel_launch(void* const* d_in, const int* in_sizes, int n_in,
                              void* d_out, int out_size) {
    int i_sc = 0;
    for (int i = 1; i < n_in; i++) if (in_sizes[i] > in_sizes[i_sc]) i_sc = i;
    int i_rs = (i_sc == 0 && n_in > 1) ? 1 : 0;
    for (int i = 0; i < n_in; i++)
        if (i != i_sc && in_sizes[i] >= 2 && in_sizes[i] <= MAX_SEG + 1) { i_rs = i; break; }

    const float* sc    = (const float*)d_in[i_sc];
    const int*   rsraw = (const int*)d_in[i_rs];
    int n    = in_sizes[i_sc];
    int nseg = in_sizes[i_rs] - 1;
    if (nseg > MAX_SEG) nseg = MAX_SEG;
    if (nseg < 1) nseg = 1;
    int nblocks = (n + CHUNK - 1) / CHUNK;
    if (nblocks > MAX_BLOCKS) nblocks = MAX_BLOCKS;
    float* out = (float*)d_out;

    int off_sel = -1, cap_sel = 0, off_nr = -1, off_bg = -1;
    if (out_size >= n + nseg + 1) {            // [sel | newrs | backgather]
        cap_sel = out_size - n - (nseg + 1);
        off_sel = 0; off_nr = cap_sel; off_bg = cap_sel + nseg + 1;
    } else if (out_size == nseg + 1) {
        off_nr = 0;
    } else if (out_size == n) {
        off_bg = 0;
    } else {
        off_sel = 0; cap_sel = out_size;
    }

    k_cfg<<<1, 256>>>(rsraw, nseg + 1);
    k_pass1<<<nblocks, TPB>>>(sc, n, nseg);
    k_fix<<<nseg, TPB>>>(sc, n, nseg);
    k_scan2<<<1, STPB>>>(nblocks, nseg, out, off_nr, out_size, n);
    k_write<<<nblocks, TPB>>>(sc, n, nseg, out, off_sel, cap_sel, off_bg, out_size);
}